// round 2
// baseline (speedup 1.0000x reference)
#include <cuda_runtime.h>
#include <math.h>

#define H 4096
#define INV_SQRT_D (1.0f / 64.0f)
#define NROWS (4 * H + 2)

// ---------------- device scratch (allocation-free) ----------------
__device__ float g_q[H];
__device__ float g_k[H];     // already scaled by 1/sqrt(d)
__device__ float g_v[H];
__device__ float g_opre[H];  // Wo@x + bo (pre-sigmoid)
__device__ float g_dots[2];  // wi.x, wf.x
__device__ float g_sc[3];    // i_gate, f_gate, 1/denom

// ---------------- reductions ----------------
__device__ __forceinline__ float warp_reduce(float v) {
    #pragma unroll
    for (int o = 16; o > 0; o >>= 1)
        v += __shfl_down_sync(0xffffffffu, v, o);
    return v;
}

__device__ __forceinline__ float block_reduce_1024(float v) {
    __shared__ float s[32];
    int lane = threadIdx.x & 31;
    int wid  = threadIdx.x >> 5;
    v = warp_reduce(v);
    if (lane == 0) s[wid] = v;
    __syncthreads();
    if (wid == 0) {
        v = s[lane];
        v = warp_reduce(v);
    }
    return v; // valid in warp 0
}

// ---------------- kernel A: all matvecs + scalar-gate dots ----------------
// One WARP per output row. 512-thread blocks (16 warps). No block barriers.
__global__ void __launch_bounds__(512)
matvec_kernel(const float* __restrict__ x,
              const float* __restrict__ Wq, const float* __restrict__ Wk,
              const float* __restrict__ Wv, const float* __restrict__ Wo,
              const float* __restrict__ bq, const float* __restrict__ bk,
              const float* __restrict__ bv, const float* __restrict__ bo,
              const float* __restrict__ wi, const float* __restrict__ wf) {
    int gw   = (blockIdx.x * 512 + threadIdx.x) >> 5;  // global warp id = row
    int lane = threadIdx.x & 31;
    if (gw >= NROWS) return;

    const float* wrow;
    if      (gw <     H) wrow = Wq + (size_t) gw          * H;
    else if (gw < 2 * H) wrow = Wk + (size_t)(gw -   H)   * H;
    else if (gw < 3 * H) wrow = Wv + (size_t)(gw - 2*H)   * H;
    else if (gw < 4 * H) wrow = Wo + (size_t)(gw - 3*H)   * H;
    else                 wrow = (gw == 4 * H) ? wi : wf;

    const float4* w4 = (const float4*)wrow;
    const float4* x4 = (const float4*)x;

    float s0 = 0.0f, s1 = 0.0f;
    #pragma unroll 8
    for (int i = 0; i < (H / 4) / 32; i += 2) {   // 32 f4 per lane, 2 accumulators
        int ia = lane + i * 32;
        int ib = lane + (i + 1) * 32;
        float4 wa = __ldcs(&w4[ia]);
        float4 wb = __ldcs(&w4[ib]);
        float4 xa = x4[ia];
        float4 xb = x4[ib];
        s0 += wa.x * xa.x + wa.y * xa.y + wa.z * xa.z + wa.w * xa.w;
        s1 += wb.x * xb.x + wb.y * xb.y + wb.z * xb.z + wb.w * xb.w;
    }
    float sum = warp_reduce(s0 + s1);

    if (lane == 0) {
        if      (gw <     H) g_q[gw]          = sum + bq[gw];
        else if (gw < 2 * H) g_k[gw -   H]    = (sum + bk[gw - H]) * INV_SQRT_D;
        else if (gw < 3 * H) g_v[gw - 2*H]    = sum + bv[gw - 2*H];
        else if (gw < 4 * H) g_opre[gw - 3*H] = sum + bo[gw - 3*H];
        else                 g_dots[gw - 4*H] = sum;
    }
}

// ---------------- kernel B: gates, n update, denom ----------------
__global__ void __launch_bounds__(1024)
gate_n_kernel(const float* __restrict__ n_prev,
              const float* __restrict__ bi, const float* __restrict__ bf,
              float* __restrict__ out_n) {
    __shared__ float s_ig, s_fg;
    int tid = threadIdx.x;
    if (tid == 0) {
        s_ig = expf(g_dots[0] + bi[0]);
        s_fg = 1.0f / (1.0f + expf(-(g_dots[1] + bf[0])));
    }
    __syncthreads();
    float ig = s_ig, fg = s_fg;

    float dot = 0.0f;
    #pragma unroll
    for (int i = 0; i < H / 1024; i++) {
        int j = tid + i * 1024;
        float nj = fg * n_prev[j] + ig * g_k[j];
        out_n[j] = nj;
        dot += nj * g_q[j];
    }
    dot = block_reduce_1024(dot);
    if (tid == 0) {
        float denom = fmaxf(fabsf(dot), 1.0f);
        g_sc[0] = ig;
        g_sc[1] = fg;
        g_sc[2] = 1.0f / denom;
    }
}

// ---------------- kernel C: C update + fused readout + output gate ----------------
// One WARP per C row. 512-thread blocks (16 warps) -> 256 blocks.
__global__ void __launch_bounds__(512)
update_kernel(const float* __restrict__ C_prev,
              float* __restrict__ out_h, float* __restrict__ out_C) {
    int row  = (blockIdx.x * 512 + threadIdx.x) >> 5;
    int lane = threadIdx.x & 31;

    float ig = g_sc[0], fg = g_sc[1], invden = g_sc[2];
    float ivr = ig * g_v[row];

    const float4* cp4 = (const float4*)(C_prev + (size_t)row * H);
    float4*       co4 = (float4*)      (out_C  + (size_t)row * H);
    const float4* k4  = (const float4*)g_k;
    const float4* q4  = (const float4*)g_q;

    float d0 = 0.0f, d1 = 0.0f;
    #pragma unroll 8
    for (int i = 0; i < (H / 4) / 32; i += 2) {
        int ia = lane + i * 32;
        int ib = lane + (i + 1) * 32;
        float4 ca = __ldcs(&cp4[ia]);
        float4 cb = __ldcs(&cp4[ib]);
        float4 ka = k4[ia];
        float4 kb = k4[ib];
        float4 qa = q4[ia];
        float4 qb = q4[ib];
        float4 na, nb;
        na.x = fg * ca.x + ivr * ka.x;
        na.y = fg * ca.y + ivr * ka.y;
        na.z = fg * ca.z + ivr * ka.z;
        na.w = fg * ca.w + ivr * ka.w;
        nb.x = fg * cb.x + ivr * kb.x;
        nb.y = fg * cb.y + ivr * kb.y;
        nb.z = fg * cb.z + ivr * kb.z;
        nb.w = fg * cb.w + ivr * kb.w;
        __stcs(&co4[ia], na);
        __stcs(&co4[ib], nb);
        d0 += na.x * qa.x + na.y * qa.y + na.z * qa.z + na.w * qa.w;
        d1 += nb.x * qb.x + nb.y * qb.y + nb.z * qb.z + nb.w * qb.w;
    }
    float dot = warp_reduce(d0 + d1);
    if (lane == 0) {
        float h_tilde = dot * invden;
        float o = 1.0f / (1.0f + expf(-g_opre[row]));
        out_h[row] = o * h_tilde;
    }
}

// ---------------- launcher ----------------
extern "C" void kernel_launch(void* const* d_in, const int* in_sizes, int n_in,
                              void* d_out, int out_size) {
    const float* x      = (const float*)d_in[0];
    // d_in[1] = h_prev (unused by mLSTM math)
    const float* C_prev = (const float*)d_in[2];
    const float* n_prev = (const float*)d_in[3];
    const float* Wq     = (const float*)d_in[4];
    const float* Wk     = (const float*)d_in[5];
    const float* Wv     = (const float*)d_in[6];
    const float* Wo     = (const float*)d_in[7];
    const float* bq     = (const float*)d_in[8];
    const float* bk     = (const float*)d_in[9];
    const float* bv     = (const float*)d_in[10];
    const float* bo     = (const float*)d_in[11];
    const float* wi     = (const float*)d_in[12];
    const float* bi     = (const float*)d_in[13];
    const float* wf     = (const float*)d_in[14];
    const float* bf     = (const float*)d_in[15];

    float* out   = (float*)d_out;
    float* out_h = out;                      // [H]
    float* out_C = out + H;                  // [H, H]
    float* out_n = out + H + (size_t)H * H;  // [H]

    int mv_blocks = (NROWS + 15) / 16;       // 16 warps per 512-thread block
    matvec_kernel<<<mv_blocks, 512>>>(x, Wq, Wk, Wv, Wo, bq, bk, bv, bo, wi, wf);
    gate_n_kernel<<<1, 1024>>>(n_prev, bi, bf, out_n);
    update_kernel<<<H / 16, 512>>>(C_prev, out_h, out_C);
}